// round 9
// baseline (speedup 1.0000x reference)
#include <cuda_runtime.h>
#include <cstdint>

// Problem constants
#define B_ROWS   1024
#define NL       64
#define NH       32
#define NG       20000
#define NC       64
#define GOI      1000
#define LOGIT_N  (GOI * NC)       // 64000
#define EPSV     1e-5f

#define MTILES     (B_ROWS / 128)        // 8
#define LOGIT_BLKS (GOI * MTILES)        // 8000
#define RHO_CTILES ((NG + 63) / 64)      // 313
#define RHO_BLKS   (RHO_CTILES * MTILES) // 2504

// Scratch (static device arrays only)
__device__ float g_h[B_ROWS * NH];   // h: tf32-rounded, kperm layout (L1-resident)
__device__ int   g_genes[GOI];

__device__ __forceinline__ uint32_t tf32r(float x) {
    uint32_t u;
    asm("cvt.rna.tf32.f32 %0, %1;" : "=r"(u) : "f"(x));
    return u;
}

// k-permutation: thread tg's 8 needed k-values become contiguous (2x float4).
// k = 8*kk + j  ->  pos = (k&3)*8 + 2*kk + (j>=4)
__device__ __forceinline__ int kperm(int k) {
    return (k & 3) * 8 + ((k >> 3) << 1) + ((k >> 2) & 1);
}

// n-permutation (within 16-col groups): a thread's paired n-fragments hold
// 4 consecutive output columns -> epilogue is pure STG.128.
__device__ __forceinline__ int p16(int n) {
    return (n & ~15) | ((n & 0x02) << 2) | ((n & 0x0C) >> 1) | (n & 1);
}

__device__ __forceinline__ void mma_tf32(float (&c)[4],
                                         uint32_t a0, uint32_t a1, uint32_t a2, uint32_t a3,
                                         uint32_t b0, uint32_t b1) {
    asm volatile(
        "mma.sync.aligned.m16n8k8.row.col.f32.tf32.tf32.f32 "
        "{%0,%1,%2,%3}, {%4,%5,%6,%7}, {%8,%9}, {%0,%1,%2,%3};"
        : "+f"(c[0]), "+f"(c[1]), "+f"(c[2]), "+f"(c[3])
        : "r"(a0), "r"(a1), "r"(a2), "r"(a3), "r"(b0), "r"(b1));
}

// ---------------------------------------------------------------------------
// Kernel 1: blocks 0..127 compute h (tf32-rounded, kperm layout);
// last block normalizes gene indices (int64 vs int32 autodetect).
// ---------------------------------------------------------------------------
__global__ void compute_h(const float* __restrict__ latent,
                          const float* __restrict__ W,
                          const float* __restrict__ bias,
                          const float* __restrict__ gamma,
                          const float* __restrict__ beta,
                          const float* __restrict__ mean,
                          const float* __restrict__ var,
                          const void*  __restrict__ genes_raw) {
    if (blockIdx.x == gridDim.x - 1) {
        __shared__ int odd_zero_cnt;
        if (threadIdx.x == 0) odd_zero_cnt = 0;
        __syncthreads();
        const int* p32 = (const int*)genes_raw;
        int local = 0;
        for (int i = threadIdx.x; i < GOI; i += blockDim.x)
            if ((i & 1) && p32[i] == 0) local++;
        if (local) atomicAdd(&odd_zero_cnt, local);
        __syncthreads();
        bool is64 = (odd_zero_cnt >= 100);
        const long long* p64 = (const long long*)genes_raw;
        for (int i = threadIdx.x; i < GOI; i += blockDim.x) {
            long long v = is64 ? p64[i] : (long long)p32[i];
            if (v < 0) v = 0;
            if (v > NG - 1) v = NG - 1;
            g_genes[i] = (int)v;
        }
        return;
    }

    __shared__ float lat_s[8][64];
    __shared__ float w_s[64][32];

    int tid = threadIdx.x;
    for (int i = tid; i < NL * NH; i += 256)
        w_s[i >> 5][i & 31] = W[i];
    int b0 = blockIdx.x * 8;
    for (int i = tid; i < 8 * NL; i += 256)
        lat_s[i >> 6][i & 63] = latent[(size_t)b0 * NL + i];
    __syncthreads();

    int br = tid >> 5;
    int j  = tid & 31;
    float s  = rsqrtf(var[j] + EPSV) * gamma[j];
    float sh = fmaf(-mean[j], s, beta[j]);
    sh = fmaf(bias[j], s, sh);
    float acc = 0.f;
#pragma unroll
    for (int l = 0; l < NL; l++)
        acc = fmaf(lat_s[br][l], w_s[l][j], acc);
    float h = fmaxf(0.f, fmaf(acc, s, sh));
    g_h[(b0 + br) * NH + kperm(j)] = __uint_as_float(tf32r(h));
}

// ---------------------------------------------------------------------------
// Kernel 2: fused GEMM, R2 grid shape (10504 independent CTAs).
//   blocks [0, 8000):    logit — gene = bx>>3, mtile = bx&7
//   blocks [8000,10504): rho   — ctile = (bx-8000)>>3, mtile = (bx-8000)&7
// CTA: 256 thr = 8 warps (4M x 2N), tile M=128 N=64 K=32, acc 32 regs/thread.
// A fragments: direct LDG.128 from L1-resident g_h (kperm layout) — no smem.
// B: staged once to smem (kperm+p16), fragments via 8x LDS.128.
// ---------------------------------------------------------------------------
__global__ __launch_bounds__(256, 4) void gemm_fused(
        const float* __restrict__ logit_table,
        const float* __restrict__ rho_table,
        float* __restrict__ out_logit,
        float* __restrict__ out_rho) {
    __shared__ float b_s[64 * 36];

    int tid = threadIdx.x;
    int bx  = blockIdx.x;

    bool is_logit = bx < LOGIT_BLKS;
    int m0, col0, ld, ncols;
    float* out;

    // --- Stage B tile (transposed + permuted + tf32) ---
    if (is_logit) {
        int gi = bx >> 3;
        m0    = (bx & 7) * 128;
        col0  = gi * NC;
        ld    = LOGIT_N;
        ncols = LOGIT_N;
        out   = out_logit;
        const float* src = logit_table + (size_t)g_genes[gi] * (NH * NC);
#pragma unroll
        for (int it = 0; it < 2; it++) {
            int q  = tid + it * 256;          // float4 index (512)
            int k  = q >> 4;                  // 16 float4 per k-row
            int n4 = (q & 15) * 4;
            float4 v = __ldg((const float4*)src + q);
            int kp = kperm(k);
            b_s[p16(n4 + 0) * 36 + kp] = __uint_as_float(tf32r(v.x));
            b_s[p16(n4 + 1) * 36 + kp] = __uint_as_float(tf32r(v.y));
            b_s[p16(n4 + 2) * 36 + kp] = __uint_as_float(tf32r(v.z));
            b_s[p16(n4 + 3) * 36 + kp] = __uint_as_float(tf32r(v.w));
        }
    } else {
        int bxr = bx - LOGIT_BLKS;
        int ct  = bxr >> 3;
        m0    = (bxr & 7) * 128;
        col0  = ct * 64;
        ld    = NG;
        ncols = NG;
        out   = out_rho;
        const float* src = rho_table + (size_t)col0 * NH;
#pragma unroll
        for (int it = 0; it < 2; it++) {
            int q  = tid + it * 256;          // float4 index (512)
            int n  = q >> 3;
            int k4 = (q & 7) * 4;
            float4 v = make_float4(0.f, 0.f, 0.f, 0.f);
            if (col0 + n < ncols)
                v = __ldg((const float4*)(src + (size_t)n * NH + k4));
            int np = p16(n) * 36;
            b_s[np + kperm(k4 + 0)] = __uint_as_float(tf32r(v.x));
            b_s[np + kperm(k4 + 1)] = __uint_as_float(tf32r(v.y));
            b_s[np + kperm(k4 + 2)] = __uint_as_float(tf32r(v.z));
            b_s[np + kperm(k4 + 3)] = __uint_as_float(tf32r(v.w));
        }
    }
    __syncthreads();

    int warp = tid >> 5, lane = tid & 31;
    int g  = lane >> 2, tg = lane & 3;
    int wm = warp >> 1, wn = warp & 1;
    int mb = wm * 32, nb = wn * 32;

    float acc[2][2][2][4];
#pragma unroll
    for (int a = 0; a < 2; a++)
#pragma unroll
        for (int b = 0; b < 2; b++)
#pragma unroll
            for (int d = 0; d < 2; d++)
#pragma unroll
                for (int e = 0; e < 4; e++)
                    acc[a][b][d][e] = 0.f;

    const float4* bu4 = (const float4*)b_s;             // row stride 9 float4
    const float4* hu4 = (const float4*)(g_h) + (size_t)m0 * 8;  // row stride 8 float4

#pragma unroll
    for (int kk2 = 0; kk2 < 2; kk2++) {
        // A fragments: direct global loads (L1-resident g_h, kperm layout)
        float4 aLo[2], aHi[2];
#pragma unroll
        for (int mf = 0; mf < 2; mf++) {
            int r = mb + mf * 16 + g;
            aLo[mf] = __ldg(hu4 + r * 8 + tg * 2 + kk2);
            aHi[mf] = __ldg(hu4 + (r + 8) * 8 + tg * 2 + kk2);
        }
#pragma unroll
        for (int p = 0; p < 2; p++)
#pragma unroll
            for (int f = 0; f < 2; f++) {
                int nrow = nb + p * 16 + f * 8 + g;
                float4 b4 = bu4[nrow * 9 + tg * 2 + kk2];
#pragma unroll
                for (int mf = 0; mf < 2; mf++) {
                    mma_tf32(acc[mf][p][f],
                             __float_as_uint(aLo[mf].x), __float_as_uint(aHi[mf].x),
                             __float_as_uint(aLo[mf].y), __float_as_uint(aHi[mf].y),
                             __float_as_uint(b4.x), __float_as_uint(b4.y));
                    mma_tf32(acc[mf][p][f],
                             __float_as_uint(aLo[mf].z), __float_as_uint(aHi[mf].z),
                             __float_as_uint(aLo[mf].w), __float_as_uint(aHi[mf].w),
                             __float_as_uint(b4.z), __float_as_uint(b4.w));
                }
            }
    }

    // --- Epilogue: STG.128 streaming stores, 4 consecutive cols/thread ---
#pragma unroll
    for (int mf = 0; mf < 2; mf++) {
#pragma unroll
        for (int p = 0; p < 2; p++) {
            int row = m0 + mb + mf * 16 + g;
            int col = col0 + nb + p * 16 + 4 * tg;
            if (col < ncols) {
                float4 v0 = make_float4(acc[mf][p][0][0], acc[mf][p][0][1],
                                        acc[mf][p][1][0], acc[mf][p][1][1]);
                float4 v1 = make_float4(acc[mf][p][0][2], acc[mf][p][0][3],
                                        acc[mf][p][1][2], acc[mf][p][1][3]);
                __stcs((float4*)(out + (size_t)row * ld + col), v0);
                __stcs((float4*)(out + (size_t)(row + 8) * ld + col), v1);
            }
        }
    }
}

// ---------------------------------------------------------------------------
// Launch
// ---------------------------------------------------------------------------
extern "C" void kernel_launch(void* const* d_in, const int* in_sizes, int n_in,
                              void* d_out, int out_size) {
    const float* latent      = (const float*)d_in[0];
    const void*  genes_raw   = d_in[1];
    const float* W           = (const float*)d_in[2];
    const float* bias        = (const float*)d_in[3];
    const float* bn_gamma    = (const float*)d_in[4];
    const float* bn_beta     = (const float*)d_in[5];
    const float* bn_mean     = (const float*)d_in[6];
    const float* bn_var      = (const float*)d_in[7];
    const float* logit_table = (const float*)d_in[8];
    const float* rho_table   = (const float*)d_in[9];

    float* out_logit = (float*)d_out;
    float* out_rho   = out_logit + (size_t)B_ROWS * LOGIT_N;

    compute_h<<<B_ROWS / 8 + 1, 256>>>(latent, W, bias, bn_gamma, bn_beta,
                                       bn_mean, bn_var, genes_raw);
    gemm_fused<<<LOGIT_BLKS + RHO_BLKS, 256>>>(logit_table, rho_table,
                                               out_logit, out_rho);
}

// round 10
// speedup vs baseline: 1.0026x; 1.0026x over previous
#include <cuda_runtime.h>
#include <cstdint>

// Problem constants
#define B_ROWS   1024
#define NL       64
#define NH       32
#define NG       20000
#define NC       64
#define GOI      1000
#define LOGIT_N  (GOI * NC)       // 64000
#define EPSV     1e-5f

#define MTILES     (B_ROWS / 128)        // 8
#define LOGIT_BLKS (GOI * MTILES)        // 8000
#define RHO_CTILES ((NG + 63) / 64)      // 313
#define RHO_BLKS   (RHO_CTILES * MTILES) // 2504

// Scratch (static device arrays only)
__device__ float g_h[B_ROWS * NH];   // h: tf32-rounded, kperm layout (L1-resident)
__device__ int   g_genes[GOI];

__device__ __forceinline__ uint32_t tf32r(float x) {
    uint32_t u;
    asm("cvt.rna.tf32.f32 %0, %1;" : "=r"(u) : "f"(x));
    return u;
}

// k-permutation: thread tg's 8 needed k-values become contiguous (2x float4).
// k = 8*kk + j  ->  pos = (k&3)*8 + 2*kk + (j>=4)
__device__ __forceinline__ int kperm(int k) {
    return (k & 3) * 8 + ((k >> 3) << 1) + ((k >> 2) & 1);
}

// n-permutation (within 16-col groups): a thread's paired n-fragments hold
// 4 consecutive output columns -> epilogue is pure STG.128.
__device__ __forceinline__ int p16(int n) {
    return (n & ~15) | ((n & 0x02) << 2) | ((n & 0x0C) >> 1) | (n & 1);
}

__device__ __forceinline__ void mma_tf32(float (&c)[4],
                                         uint32_t a0, uint32_t a1, uint32_t a2, uint32_t a3,
                                         uint32_t b0, uint32_t b1) {
    asm volatile(
        "mma.sync.aligned.m16n8k8.row.col.f32.tf32.tf32.f32 "
        "{%0,%1,%2,%3}, {%4,%5,%6,%7}, {%8,%9}, {%0,%1,%2,%3};"
        : "+f"(c[0]), "+f"(c[1]), "+f"(c[2]), "+f"(c[3])
        : "r"(a0), "r"(a1), "r"(a2), "r"(a3), "r"(b0), "r"(b1));
}

// ---------------------------------------------------------------------------
// Kernel 1: blocks 0..127 compute h (tf32-rounded, kperm layout);
// last block normalizes gene indices (int64 vs int32 autodetect).
// ---------------------------------------------------------------------------
__global__ void compute_h(const float* __restrict__ latent,
                          const float* __restrict__ W,
                          const float* __restrict__ bias,
                          const float* __restrict__ gamma,
                          const float* __restrict__ beta,
                          const float* __restrict__ mean,
                          const float* __restrict__ var,
                          const void*  __restrict__ genes_raw) {
    if (blockIdx.x == gridDim.x - 1) {
        __shared__ int odd_zero_cnt;
        if (threadIdx.x == 0) odd_zero_cnt = 0;
        __syncthreads();
        const int* p32 = (const int*)genes_raw;
        int local = 0;
        for (int i = threadIdx.x; i < GOI; i += blockDim.x)
            if ((i & 1) && p32[i] == 0) local++;
        if (local) atomicAdd(&odd_zero_cnt, local);
        __syncthreads();
        bool is64 = (odd_zero_cnt >= 100);
        const long long* p64 = (const long long*)genes_raw;
        for (int i = threadIdx.x; i < GOI; i += blockDim.x) {
            long long v = is64 ? p64[i] : (long long)p32[i];
            if (v < 0) v = 0;
            if (v > NG - 1) v = NG - 1;
            g_genes[i] = (int)v;
        }
        return;
    }

    __shared__ float lat_s[8][64];
    __shared__ float w_s[64][32];

    int tid = threadIdx.x;
    for (int i = tid; i < NL * NH; i += 256)
        w_s[i >> 5][i & 31] = W[i];
    int b0 = blockIdx.x * 8;
    for (int i = tid; i < 8 * NL; i += 256)
        lat_s[i >> 6][i & 63] = latent[(size_t)b0 * NL + i];
    __syncthreads();

    int br = tid >> 5;
    int j  = tid & 31;
    float s  = rsqrtf(var[j] + EPSV) * gamma[j];
    float sh = fmaf(-mean[j], s, beta[j]);
    sh = fmaf(bias[j], s, sh);
    float acc = 0.f;
#pragma unroll
    for (int l = 0; l < NL; l++)
        acc = fmaf(lat_s[br][l], w_s[l][j], acc);
    float h = fmaxf(0.f, fmaf(acc, s, sh));
    g_h[(b0 + br) * NH + kperm(j)] = __uint_as_float(tf32r(h));
}

// ---------------------------------------------------------------------------
// Kernel 2: fused GEMM, R2 grid shape (10504 independent CTAs).
//   blocks [0, 8000):    logit — gene = bx>>3, mtile = bx&7
//   blocks [8000,10504): rho   — ctile = (bx-8000)>>3, mtile = (bx-8000)&7
// CTA: 256 thr = 8 warps (4M x 2N), tile M=128 N=64 K=32, acc 32 regs/thread.
// A fragments: direct LDG.128 from L1-resident g_h (kperm layout) — no smem.
// B: staged once to smem (kperm+p16), fragments via 8x LDS.128.
// ---------------------------------------------------------------------------
__global__ __launch_bounds__(256, 4) void gemm_fused(
        const float* __restrict__ logit_table,
        const float* __restrict__ rho_table,
        float* __restrict__ out_logit,
        float* __restrict__ out_rho) {
    __shared__ float b_s[64 * 36];

    int tid = threadIdx.x;
    int bx  = blockIdx.x;

    bool is_logit = bx < LOGIT_BLKS;
    int m0, col0, ld, ncols;
    float* out;

    // --- Stage B tile (transposed + permuted + tf32) ---
    if (is_logit) {
        int gi = bx >> 3;
        m0    = (bx & 7) * 128;
        col0  = gi * NC;
        ld    = LOGIT_N;
        ncols = LOGIT_N;
        out   = out_logit;
        const float* src = logit_table + (size_t)g_genes[gi] * (NH * NC);
#pragma unroll
        for (int it = 0; it < 2; it++) {
            int q  = tid + it * 256;          // float4 index (512)
            int k  = q >> 4;                  // 16 float4 per k-row
            int n4 = (q & 15) * 4;
            float4 v = __ldg((const float4*)src + q);
            int kp = kperm(k);
            b_s[p16(n4 + 0) * 36 + kp] = __uint_as_float(tf32r(v.x));
            b_s[p16(n4 + 1) * 36 + kp] = __uint_as_float(tf32r(v.y));
            b_s[p16(n4 + 2) * 36 + kp] = __uint_as_float(tf32r(v.z));
            b_s[p16(n4 + 3) * 36 + kp] = __uint_as_float(tf32r(v.w));
        }
    } else {
        int bxr = bx - LOGIT_BLKS;
        int ct  = bxr >> 3;
        m0    = (bxr & 7) * 128;
        col0  = ct * 64;
        ld    = NG;
        ncols = NG;
        out   = out_rho;
        const float* src = rho_table + (size_t)col0 * NH;
#pragma unroll
        for (int it = 0; it < 2; it++) {
            int q  = tid + it * 256;          // float4 index (512)
            int n  = q >> 3;
            int k4 = (q & 7) * 4;
            float4 v = make_float4(0.f, 0.f, 0.f, 0.f);
            if (col0 + n < ncols)
                v = __ldg((const float4*)(src + (size_t)n * NH + k4));
            int np = p16(n) * 36;
            b_s[np + kperm(k4 + 0)] = __uint_as_float(tf32r(v.x));
            b_s[np + kperm(k4 + 1)] = __uint_as_float(tf32r(v.y));
            b_s[np + kperm(k4 + 2)] = __uint_as_float(tf32r(v.z));
            b_s[np + kperm(k4 + 3)] = __uint_as_float(tf32r(v.w));
        }
    }
    __syncthreads();

    int warp = tid >> 5, lane = tid & 31;
    int g  = lane >> 2, tg = lane & 3;
    int wm = warp >> 1, wn = warp & 1;
    int mb = wm * 32, nb = wn * 32;

    float acc[2][2][2][4];
#pragma unroll
    for (int a = 0; a < 2; a++)
#pragma unroll
        for (int b = 0; b < 2; b++)
#pragma unroll
            for (int d = 0; d < 2; d++)
#pragma unroll
                for (int e = 0; e < 4; e++)
                    acc[a][b][d][e] = 0.f;

    const float4* bu4 = (const float4*)b_s;             // row stride 9 float4
    const float4* hu4 = (const float4*)(g_h) + (size_t)m0 * 8;  // row stride 8 float4

#pragma unroll
    for (int kk2 = 0; kk2 < 2; kk2++) {
        // A fragments: direct global loads (L1-resident g_h, kperm layout)
        float4 aLo[2], aHi[2];
#pragma unroll
        for (int mf = 0; mf < 2; mf++) {
            int r = mb + mf * 16 + g;
            aLo[mf] = __ldg(hu4 + r * 8 + tg * 2 + kk2);
            aHi[mf] = __ldg(hu4 + (r + 8) * 8 + tg * 2 + kk2);
        }
#pragma unroll
        for (int p = 0; p < 2; p++)
#pragma unroll
            for (int f = 0; f < 2; f++) {
                int nrow = nb + p * 16 + f * 8 + g;
                float4 b4 = bu4[nrow * 9 + tg * 2 + kk2];
#pragma unroll
                for (int mf = 0; mf < 2; mf++) {
                    mma_tf32(acc[mf][p][f],
                             __float_as_uint(aLo[mf].x), __float_as_uint(aHi[mf].x),
                             __float_as_uint(aLo[mf].y), __float_as_uint(aHi[mf].y),
                             __float_as_uint(b4.x), __float_as_uint(b4.y));
                    mma_tf32(acc[mf][p][f],
                             __float_as_uint(aLo[mf].z), __float_as_uint(aHi[mf].z),
                             __float_as_uint(aLo[mf].w), __float_as_uint(aHi[mf].w),
                             __float_as_uint(b4.z), __float_as_uint(b4.w));
                }
            }
    }

    // --- Epilogue: STG.128 streaming stores, 4 consecutive cols/thread ---
#pragma unroll
    for (int mf = 0; mf < 2; mf++) {
#pragma unroll
        for (int p = 0; p < 2; p++) {
            int row = m0 + mb + mf * 16 + g;
            int col = col0 + nb + p * 16 + 4 * tg;
            if (col < ncols) {
                float4 v0 = make_float4(acc[mf][p][0][0], acc[mf][p][0][1],
                                        acc[mf][p][1][0], acc[mf][p][1][1]);
                float4 v1 = make_float4(acc[mf][p][0][2], acc[mf][p][0][3],
                                        acc[mf][p][1][2], acc[mf][p][1][3]);
                __stcs((float4*)(out + (size_t)row * ld + col), v0);
                __stcs((float4*)(out + (size_t)(row + 8) * ld + col), v1);
            }
        }
    }
}

// ---------------------------------------------------------------------------
// Launch
// ---------------------------------------------------------------------------
extern "C" void kernel_launch(void* const* d_in, const int* in_sizes, int n_in,
                              void* d_out, int out_size) {
    const float* latent      = (const float*)d_in[0];
    const void*  genes_raw   = d_in[1];
    const float* W           = (const float*)d_in[2];
    const float* bias        = (const float*)d_in[3];
    const float* bn_gamma    = (const float*)d_in[4];
    const float* bn_beta     = (const float*)d_in[5];
    const float* bn_mean     = (const float*)d_in[6];
    const float* bn_var      = (const float*)d_in[7];
    const float* logit_table = (const float*)d_in[8];
    const float* rho_table   = (const float*)d_in[9];

    float* out_logit = (float*)d_out;
    float* out_rho   = out_logit + (size_t)B_ROWS * LOGIT_N;

    compute_h<<<B_ROWS / 8 + 1, 256>>>(latent, W, bias, bn_gamma, bn_beta,
                                       bn_mean, bn_var, genes_raw);
    gemm_fused<<<LOGIT_BLKS + RHO_BLKS, 256>>>(logit_table, rho_table,
                                               out_logit, out_rho);
}

// round 11
// speedup vs baseline: 1.0103x; 1.0077x over previous
#include <cuda_runtime.h>
#include <cstdint>

// Problem constants
#define B_ROWS   1024
#define NL       64
#define NH       32
#define NG       20000
#define NC       64
#define GOI      1000
#define LOGIT_N  (GOI * NC)       // 64000
#define EPSV     1e-5f

#define MTILES     (B_ROWS / 128)        // 8
#define LOGIT_BLKS (GOI * MTILES)        // 8000
#define RHO_CTILES ((NG + 63) / 64)      // 313
#define RHO_BLKS   (RHO_CTILES * MTILES) // 2504

// Scratch (static device arrays only)
__device__ float g_h[B_ROWS * NH];   // h: tf32-rounded, kperm layout (L1-resident)
__device__ int   g_genes[GOI];

__device__ __forceinline__ uint32_t tf32r(float x) {
    uint32_t u;
    asm("cvt.rna.tf32.f32 %0, %1;" : "=r"(u) : "f"(x));
    return u;
}

// k-permutation: thread tg's 8 needed k-values become contiguous (2x float4).
// k = 8*kk + j  ->  pos = (k&3)*8 + 2*kk + (j>=4)
__device__ __forceinline__ int kperm(int k) {
    return (k & 3) * 8 + ((k >> 3) << 1) + ((k >> 2) & 1);
}

// n-permutation (within 16-col groups): a thread's paired n-fragments hold
// 4 consecutive output columns -> epilogue is pure STG.128.
__device__ __forceinline__ int p16(int n) {
    return (n & ~15) | ((n & 0x02) << 2) | ((n & 0x0C) >> 1) | (n & 1);
}

__device__ __forceinline__ void mma_tf32(float (&c)[4],
                                         uint32_t a0, uint32_t a1, uint32_t a2, uint32_t a3,
                                         uint32_t b0, uint32_t b1) {
    asm volatile(
        "mma.sync.aligned.m16n8k8.row.col.f32.tf32.tf32.f32 "
        "{%0,%1,%2,%3}, {%4,%5,%6,%7}, {%8,%9}, {%0,%1,%2,%3};"
        : "+f"(c[0]), "+f"(c[1]), "+f"(c[2]), "+f"(c[3])
        : "r"(a0), "r"(a1), "r"(a2), "r"(a3), "r"(b0), "r"(b1));
}

// ---------------------------------------------------------------------------
// Kernel 1: blocks 0..127 compute h (tf32-rounded, kperm layout);
// last block normalizes gene indices (int64 vs int32 autodetect).
// ---------------------------------------------------------------------------
__global__ void compute_h(const float* __restrict__ latent,
                          const float* __restrict__ W,
                          const float* __restrict__ bias,
                          const float* __restrict__ gamma,
                          const float* __restrict__ beta,
                          const float* __restrict__ mean,
                          const float* __restrict__ var,
                          const void*  __restrict__ genes_raw) {
    if (blockIdx.x == gridDim.x - 1) {
        __shared__ int odd_zero_cnt;
        if (threadIdx.x == 0) odd_zero_cnt = 0;
        __syncthreads();
        const int* p32 = (const int*)genes_raw;
        int local = 0;
        for (int i = threadIdx.x; i < GOI; i += blockDim.x)
            if ((i & 1) && p32[i] == 0) local++;
        if (local) atomicAdd(&odd_zero_cnt, local);
        __syncthreads();
        bool is64 = (odd_zero_cnt >= 100);
        const long long* p64 = (const long long*)genes_raw;
        for (int i = threadIdx.x; i < GOI; i += blockDim.x) {
            long long v = is64 ? p64[i] : (long long)p32[i];
            if (v < 0) v = 0;
            if (v > NG - 1) v = NG - 1;
            g_genes[i] = (int)v;
        }
        return;
    }

    __shared__ float lat_s[8][64];
    __shared__ float w_s[64][32];

    int tid = threadIdx.x;
    for (int i = tid; i < NL * NH; i += 256)
        w_s[i >> 5][i & 31] = W[i];
    int b0 = blockIdx.x * 8;
    for (int i = tid; i < 8 * NL; i += 256)
        lat_s[i >> 6][i & 63] = latent[(size_t)b0 * NL + i];
    __syncthreads();

    int br = tid >> 5;
    int j  = tid & 31;
    float s  = rsqrtf(var[j] + EPSV) * gamma[j];
    float sh = fmaf(-mean[j], s, beta[j]);
    sh = fmaf(bias[j], s, sh);
    float acc = 0.f;
#pragma unroll
    for (int l = 0; l < NL; l++)
        acc = fmaf(lat_s[br][l], w_s[l][j], acc);
    float h = fmaxf(0.f, fmaf(acc, s, sh));
    g_h[(b0 + br) * NH + kperm(j)] = __uint_as_float(tf32r(h));
}

// ---------------------------------------------------------------------------
// Kernel 2: fused GEMM, R2 grid shape (10504 independent CTAs).
//   blocks [0, 8000):    logit — gene = bx>>3, mtile = bx&7
//   blocks [8000,10504): rho   — ctile = (bx-8000)>>3, mtile = (bx-8000)&7
// CTA: 256 thr = 8 warps (4M x 2N), tile M=128 N=64 K=32, acc 32 regs/thread.
// A fragments: direct LDG.128 from L1-resident g_h (kperm layout) — no smem.
// B: staged once to smem (kperm+p16), fragments via 8x LDS.128.
// ---------------------------------------------------------------------------
__global__ __launch_bounds__(256, 4) void gemm_fused(
        const float* __restrict__ logit_table,
        const float* __restrict__ rho_table,
        float* __restrict__ out_logit,
        float* __restrict__ out_rho) {
    __shared__ float b_s[64 * 36];

    int tid = threadIdx.x;
    int bx  = blockIdx.x;

    bool is_logit = bx < LOGIT_BLKS;
    int m0, col0, ld, ncols;
    float* out;

    // --- Stage B tile (transposed + permuted + tf32) ---
    if (is_logit) {
        int gi = bx >> 3;
        m0    = (bx & 7) * 128;
        col0  = gi * NC;
        ld    = LOGIT_N;
        ncols = LOGIT_N;
        out   = out_logit;
        const float* src = logit_table + (size_t)g_genes[gi] * (NH * NC);
#pragma unroll
        for (int it = 0; it < 2; it++) {
            int q  = tid + it * 256;          // float4 index (512)
            int k  = q >> 4;                  // 16 float4 per k-row
            int n4 = (q & 15) * 4;
            float4 v = __ldg((const float4*)src + q);
            int kp = kperm(k);
            b_s[p16(n4 + 0) * 36 + kp] = __uint_as_float(tf32r(v.x));
            b_s[p16(n4 + 1) * 36 + kp] = __uint_as_float(tf32r(v.y));
            b_s[p16(n4 + 2) * 36 + kp] = __uint_as_float(tf32r(v.z));
            b_s[p16(n4 + 3) * 36 + kp] = __uint_as_float(tf32r(v.w));
        }
    } else {
        int bxr = bx - LOGIT_BLKS;
        int ct  = bxr >> 3;
        m0    = (bxr & 7) * 128;
        col0  = ct * 64;
        ld    = NG;
        ncols = NG;
        out   = out_rho;
        const float* src = rho_table + (size_t)col0 * NH;
#pragma unroll
        for (int it = 0; it < 2; it++) {
            int q  = tid + it * 256;          // float4 index (512)
            int n  = q >> 3;
            int k4 = (q & 7) * 4;
            float4 v = make_float4(0.f, 0.f, 0.f, 0.f);
            if (col0 + n < ncols)
                v = __ldg((const float4*)(src + (size_t)n * NH + k4));
            int np = p16(n) * 36;
            b_s[np + kperm(k4 + 0)] = __uint_as_float(tf32r(v.x));
            b_s[np + kperm(k4 + 1)] = __uint_as_float(tf32r(v.y));
            b_s[np + kperm(k4 + 2)] = __uint_as_float(tf32r(v.z));
            b_s[np + kperm(k4 + 3)] = __uint_as_float(tf32r(v.w));
        }
    }
    __syncthreads();

    int warp = tid >> 5, lane = tid & 31;
    int g  = lane >> 2, tg = lane & 3;
    int wm = warp >> 1, wn = warp & 1;
    int mb = wm * 32, nb = wn * 32;

    float acc[2][2][2][4];
#pragma unroll
    for (int a = 0; a < 2; a++)
#pragma unroll
        for (int b = 0; b < 2; b++)
#pragma unroll
            for (int d = 0; d < 2; d++)
#pragma unroll
                for (int e = 0; e < 4; e++)
                    acc[a][b][d][e] = 0.f;

    const float4* bu4 = (const float4*)b_s;             // row stride 9 float4
    const float4* hu4 = (const float4*)(g_h) + (size_t)m0 * 8;  // row stride 8 float4

#pragma unroll
    for (int kk2 = 0; kk2 < 2; kk2++) {
        // A fragments: direct global loads (L1-resident g_h, kperm layout)
        float4 aLo[2], aHi[2];
#pragma unroll
        for (int mf = 0; mf < 2; mf++) {
            int r = mb + mf * 16 + g;
            aLo[mf] = __ldg(hu4 + r * 8 + tg * 2 + kk2);
            aHi[mf] = __ldg(hu4 + (r + 8) * 8 + tg * 2 + kk2);
        }
#pragma unroll
        for (int p = 0; p < 2; p++)
#pragma unroll
            for (int f = 0; f < 2; f++) {
                int nrow = nb + p * 16 + f * 8 + g;
                float4 b4 = bu4[nrow * 9 + tg * 2 + kk2];
#pragma unroll
                for (int mf = 0; mf < 2; mf++) {
                    mma_tf32(acc[mf][p][f],
                             __float_as_uint(aLo[mf].x), __float_as_uint(aHi[mf].x),
                             __float_as_uint(aLo[mf].y), __float_as_uint(aHi[mf].y),
                             __float_as_uint(b4.x), __float_as_uint(b4.y));
                    mma_tf32(acc[mf][p][f],
                             __float_as_uint(aLo[mf].z), __float_as_uint(aHi[mf].z),
                             __float_as_uint(aLo[mf].w), __float_as_uint(aHi[mf].w),
                             __float_as_uint(b4.z), __float_as_uint(b4.w));
                }
            }
    }

    // --- Epilogue: STG.128 streaming stores, 4 consecutive cols/thread ---
#pragma unroll
    for (int mf = 0; mf < 2; mf++) {
#pragma unroll
        for (int p = 0; p < 2; p++) {
            int row = m0 + mb + mf * 16 + g;
            int col = col0 + nb + p * 16 + 4 * tg;
            if (col < ncols) {
                float4 v0 = make_float4(acc[mf][p][0][0], acc[mf][p][0][1],
                                        acc[mf][p][1][0], acc[mf][p][1][1]);
                float4 v1 = make_float4(acc[mf][p][0][2], acc[mf][p][0][3],
                                        acc[mf][p][1][2], acc[mf][p][1][3]);
                __stcs((float4*)(out + (size_t)row * ld + col), v0);
                __stcs((float4*)(out + (size_t)(row + 8) * ld + col), v1);
            }
        }
    }
}

// ---------------------------------------------------------------------------
// Launch
// ---------------------------------------------------------------------------
extern "C" void kernel_launch(void* const* d_in, const int* in_sizes, int n_in,
                              void* d_out, int out_size) {
    const float* latent      = (const float*)d_in[0];
    const void*  genes_raw   = d_in[1];
    const float* W           = (const float*)d_in[2];
    const float* bias        = (const float*)d_in[3];
    const float* bn_gamma    = (const float*)d_in[4];
    const float* bn_beta     = (const float*)d_in[5];
    const float* bn_mean     = (const float*)d_in[6];
    const float* bn_var      = (const float*)d_in[7];
    const float* logit_table = (const float*)d_in[8];
    const float* rho_table   = (const float*)d_in[9];

    float* out_logit = (float*)d_out;
    float* out_rho   = out_logit + (size_t)B_ROWS * LOGIT_N;

    compute_h<<<B_ROWS / 8 + 1, 256>>>(latent, W, bias, bn_gamma, bn_beta,
                                       bn_mean, bn_var, genes_raw);
    gemm_fused<<<LOGIT_BLKS + RHO_BLKS, 256>>>(logit_table, rho_table,
                                               out_logit, out_rho);
}

// round 12
// speedup vs baseline: 1.0155x; 1.0052x over previous
#include <cuda_runtime.h>
#include <cstdint>

// Problem constants
#define B_ROWS   1024
#define NL       64
#define NH       32
#define NG       20000
#define NC       64
#define GOI      1000
#define LOGIT_N  (GOI * NC)       // 64000
#define EPSV     1e-5f

#define MTILES     (B_ROWS / 128)        // 8
#define LOGIT_BLKS (GOI * MTILES)        // 8000
#define RHO_CTILES ((NG + 63) / 64)      // 313
#define RHO_BLKS   (RHO_CTILES * MTILES) // 2504

// Scratch (static device arrays only)
__device__ float g_h[B_ROWS * NH];   // h: tf32-rounded, kperm layout (L1-resident)
__device__ int   g_genes[GOI];

__device__ __forceinline__ uint32_t tf32r(float x) {
    uint32_t u;
    asm("cvt.rna.tf32.f32 %0, %1;" : "=r"(u) : "f"(x));
    return u;
}

// k-permutation: thread tg's 8 needed k-values become contiguous (2x float4).
// k = 8*kk + j  ->  pos = (k&3)*8 + 2*kk + (j>=4)
__device__ __forceinline__ int kperm(int k) {
    return (k & 3) * 8 + ((k >> 3) << 1) + ((k >> 2) & 1);
}

// n-permutation (within 16-col groups): a thread's paired n-fragments hold
// 4 consecutive output columns -> epilogue is pure STG.128.
__device__ __forceinline__ int p16(int n) {
    return (n & ~15) | ((n & 0x02) << 2) | ((n & 0x0C) >> 1) | (n & 1);
}

__device__ __forceinline__ void mma_tf32(float (&c)[4],
                                         uint32_t a0, uint32_t a1, uint32_t a2, uint32_t a3,
                                         uint32_t b0, uint32_t b1) {
    asm volatile(
        "mma.sync.aligned.m16n8k8.row.col.f32.tf32.tf32.f32 "
        "{%0,%1,%2,%3}, {%4,%5,%6,%7}, {%8,%9}, {%0,%1,%2,%3};"
        : "+f"(c[0]), "+f"(c[1]), "+f"(c[2]), "+f"(c[3])
        : "r"(a0), "r"(a1), "r"(a2), "r"(a3), "r"(b0), "r"(b1));
}

// ---------------------------------------------------------------------------
// Kernel 1: blocks 0..127 compute h (tf32-rounded, kperm layout);
// last block normalizes gene indices (int64 vs int32 autodetect).
// ---------------------------------------------------------------------------
__global__ void compute_h(const float* __restrict__ latent,
                          const float* __restrict__ W,
                          const float* __restrict__ bias,
                          const float* __restrict__ gamma,
                          const float* __restrict__ beta,
                          const float* __restrict__ mean,
                          const float* __restrict__ var,
                          const void*  __restrict__ genes_raw) {
    if (blockIdx.x == gridDim.x - 1) {
        __shared__ int odd_zero_cnt;
        if (threadIdx.x == 0) odd_zero_cnt = 0;
        __syncthreads();
        const int* p32 = (const int*)genes_raw;
        int local = 0;
        for (int i = threadIdx.x; i < GOI; i += blockDim.x)
            if ((i & 1) && p32[i] == 0) local++;
        if (local) atomicAdd(&odd_zero_cnt, local);
        __syncthreads();
        bool is64 = (odd_zero_cnt >= 100);
        const long long* p64 = (const long long*)genes_raw;
        for (int i = threadIdx.x; i < GOI; i += blockDim.x) {
            long long v = is64 ? p64[i] : (long long)p32[i];
            if (v < 0) v = 0;
            if (v > NG - 1) v = NG - 1;
            g_genes[i] = (int)v;
        }
        return;
    }

    __shared__ float lat_s[8][64];
    __shared__ float w_s[64][32];

    int tid = threadIdx.x;
    for (int i = tid; i < NL * NH; i += 256)
        w_s[i >> 5][i & 31] = W[i];
    int b0 = blockIdx.x * 8;
    for (int i = tid; i < 8 * NL; i += 256)
        lat_s[i >> 6][i & 63] = latent[(size_t)b0 * NL + i];
    __syncthreads();

    int br = tid >> 5;
    int j  = tid & 31;
    float s  = rsqrtf(var[j] + EPSV) * gamma[j];
    float sh = fmaf(-mean[j], s, beta[j]);
    sh = fmaf(bias[j], s, sh);
    float acc = 0.f;
#pragma unroll
    for (int l = 0; l < NL; l++)
        acc = fmaf(lat_s[br][l], w_s[l][j], acc);
    float h = fmaxf(0.f, fmaf(acc, s, sh));
    g_h[(b0 + br) * NH + kperm(j)] = __uint_as_float(tf32r(h));
}

// ---------------------------------------------------------------------------
// Kernel 2: fused GEMM, R2 grid shape (10504 independent CTAs).
//   blocks [0, 8000):    logit — gene = bx>>3, mtile = bx&7
//   blocks [8000,10504): rho   — ctile = (bx-8000)>>3, mtile = (bx-8000)&7
// CTA: 256 thr = 8 warps (4M x 2N), tile M=128 N=64 K=32, acc 32 regs/thread.
// A fragments: direct LDG.128 from L1-resident g_h (kperm layout) — no smem.
// B: staged once to smem (kperm+p16), fragments via 8x LDS.128.
// ---------------------------------------------------------------------------
__global__ __launch_bounds__(256, 4) void gemm_fused(
        const float* __restrict__ logit_table,
        const float* __restrict__ rho_table,
        float* __restrict__ out_logit,
        float* __restrict__ out_rho) {
    __shared__ float b_s[64 * 36];

    int tid = threadIdx.x;
    int bx  = blockIdx.x;

    bool is_logit = bx < LOGIT_BLKS;
    int m0, col0, ld, ncols;
    float* out;

    // --- Stage B tile (transposed + permuted + tf32) ---
    if (is_logit) {
        int gi = bx >> 3;
        m0    = (bx & 7) * 128;
        col0  = gi * NC;
        ld    = LOGIT_N;
        ncols = LOGIT_N;
        out   = out_logit;
        const float* src = logit_table + (size_t)g_genes[gi] * (NH * NC);
#pragma unroll
        for (int it = 0; it < 2; it++) {
            int q  = tid + it * 256;          // float4 index (512)
            int k  = q >> 4;                  // 16 float4 per k-row
            int n4 = (q & 15) * 4;
            float4 v = __ldg((const float4*)src + q);
            int kp = kperm(k);
            b_s[p16(n4 + 0) * 36 + kp] = __uint_as_float(tf32r(v.x));
            b_s[p16(n4 + 1) * 36 + kp] = __uint_as_float(tf32r(v.y));
            b_s[p16(n4 + 2) * 36 + kp] = __uint_as_float(tf32r(v.z));
            b_s[p16(n4 + 3) * 36 + kp] = __uint_as_float(tf32r(v.w));
        }
    } else {
        int bxr = bx - LOGIT_BLKS;
        int ct  = bxr >> 3;
        m0    = (bxr & 7) * 128;
        col0  = ct * 64;
        ld    = NG;
        ncols = NG;
        out   = out_rho;
        const float* src = rho_table + (size_t)col0 * NH;
#pragma unroll
        for (int it = 0; it < 2; it++) {
            int q  = tid + it * 256;          // float4 index (512)
            int n  = q >> 3;
            int k4 = (q & 7) * 4;
            float4 v = make_float4(0.f, 0.f, 0.f, 0.f);
            if (col0 + n < ncols)
                v = __ldg((const float4*)(src + (size_t)n * NH + k4));
            int np = p16(n) * 36;
            b_s[np + kperm(k4 + 0)] = __uint_as_float(tf32r(v.x));
            b_s[np + kperm(k4 + 1)] = __uint_as_float(tf32r(v.y));
            b_s[np + kperm(k4 + 2)] = __uint_as_float(tf32r(v.z));
            b_s[np + kperm(k4 + 3)] = __uint_as_float(tf32r(v.w));
        }
    }
    __syncthreads();

    int warp = tid >> 5, lane = tid & 31;
    int g  = lane >> 2, tg = lane & 3;
    int wm = warp >> 1, wn = warp & 1;
    int mb = wm * 32, nb = wn * 32;

    float acc[2][2][2][4];
#pragma unroll
    for (int a = 0; a < 2; a++)
#pragma unroll
        for (int b = 0; b < 2; b++)
#pragma unroll
            for (int d = 0; d < 2; d++)
#pragma unroll
                for (int e = 0; e < 4; e++)
                    acc[a][b][d][e] = 0.f;

    const float4* bu4 = (const float4*)b_s;             // row stride 9 float4
    const float4* hu4 = (const float4*)(g_h) + (size_t)m0 * 8;  // row stride 8 float4

#pragma unroll
    for (int kk2 = 0; kk2 < 2; kk2++) {
        // A fragments: direct global loads (L1-resident g_h, kperm layout)
        float4 aLo[2], aHi[2];
#pragma unroll
        for (int mf = 0; mf < 2; mf++) {
            int r = mb + mf * 16 + g;
            aLo[mf] = __ldg(hu4 + r * 8 + tg * 2 + kk2);
            aHi[mf] = __ldg(hu4 + (r + 8) * 8 + tg * 2 + kk2);
        }
#pragma unroll
        for (int p = 0; p < 2; p++)
#pragma unroll
            for (int f = 0; f < 2; f++) {
                int nrow = nb + p * 16 + f * 8 + g;
                float4 b4 = bu4[nrow * 9 + tg * 2 + kk2];
#pragma unroll
                for (int mf = 0; mf < 2; mf++) {
                    mma_tf32(acc[mf][p][f],
                             __float_as_uint(aLo[mf].x), __float_as_uint(aHi[mf].x),
                             __float_as_uint(aLo[mf].y), __float_as_uint(aHi[mf].y),
                             __float_as_uint(b4.x), __float_as_uint(b4.y));
                    mma_tf32(acc[mf][p][f],
                             __float_as_uint(aLo[mf].z), __float_as_uint(aHi[mf].z),
                             __float_as_uint(aLo[mf].w), __float_as_uint(aHi[mf].w),
                             __float_as_uint(b4.z), __float_as_uint(b4.w));
                }
            }
    }

    // --- Epilogue: STG.128 streaming stores, 4 consecutive cols/thread ---
#pragma unroll
    for (int mf = 0; mf < 2; mf++) {
#pragma unroll
        for (int p = 0; p < 2; p++) {
            int row = m0 + mb + mf * 16 + g;
            int col = col0 + nb + p * 16 + 4 * tg;
            if (col < ncols) {
                float4 v0 = make_float4(acc[mf][p][0][0], acc[mf][p][0][1],
                                        acc[mf][p][1][0], acc[mf][p][1][1]);
                float4 v1 = make_float4(acc[mf][p][0][2], acc[mf][p][0][3],
                                        acc[mf][p][1][2], acc[mf][p][1][3]);
                __stcs((float4*)(out + (size_t)row * ld + col), v0);
                __stcs((float4*)(out + (size_t)(row + 8) * ld + col), v1);
            }
        }
    }
}

// ---------------------------------------------------------------------------
// Launch
// ---------------------------------------------------------------------------
extern "C" void kernel_launch(void* const* d_in, const int* in_sizes, int n_in,
                              void* d_out, int out_size) {
    const float* latent      = (const float*)d_in[0];
    const void*  genes_raw   = d_in[1];
    const float* W           = (const float*)d_in[2];
    const float* bias        = (const float*)d_in[3];
    const float* bn_gamma    = (const float*)d_in[4];
    const float* bn_beta     = (const float*)d_in[5];
    const float* bn_mean     = (const float*)d_in[6];
    const float* bn_var      = (const float*)d_in[7];
    const float* logit_table = (const float*)d_in[8];
    const float* rho_table   = (const float*)d_in[9];

    float* out_logit = (float*)d_out;
    float* out_rho   = out_logit + (size_t)B_ROWS * LOGIT_N;

    compute_h<<<B_ROWS / 8 + 1, 256>>>(latent, W, bias, bn_gamma, bn_beta,
                                       bn_mean, bn_var, genes_raw);
    gemm_fused<<<LOGIT_BLKS + RHO_BLKS, 256>>>(logit_table, rho_table,
                                               out_logit, out_rho);
}